// round 1
// baseline (speedup 1.0000x reference)
#include <cuda_runtime.h>
#include <math.h>

#define NBK 5     // number of LSTM blocks
#define HD  32    // hidden size
#define DIN 4     // input features
#define TT  25    // total timesteps
#define HIDD 64   // MLP hidden
#define TPB 128   // threads per CTA = samples per CTA

// Shared-memory layout. Gate weights interleaved (j, k, [i,f,g,o]) so a single
// LDS.128 broadcast feeds 4 FFMAs. State arrays are [k][tid] so lane accesses
// are consecutive (conflict-free).
struct SmemLayout {
    float Wp0[HD][DIN][4];   //  512 f : Wih0 interleaved
    float Wh0[HD][HD][4];    // 4096 f : Whh0 interleaved
    float Wp1[HD][HD][4];    // 4096 f : Wih1 interleaved
    float Wh1[HD][HD][4];    // 4096 f : Whh1 interleaved
    float b0[HD][4];         //  128 f : bih0+bhh0
    float b1r[HD][4];        //  128 f : bih1+bhh1
    float W1s[HIDD * HD];    // 2048 f
    float b1s[HIDD];         //   64 f
    float W2s[HIDD * HIDD];  // 4096 f
    float b2s[HIDD];         //   64 f
    float hs0[HD][TPB];      // 4096 f : layer-0 h state, [k][tid]
    float hs1[HD][TPB];      // 4096 f : layer-1 h state
};                           // total 27520 floats = 110080 B -> 2 CTAs/SM

__device__ __forceinline__ float sigf(float v) {
    return 1.0f / (1.0f + __expf(-v));
}
__device__ __forceinline__ float tanhr(float v) {
    // tanh(x) = 2*sigmoid(2x) - 1 ; error ~1e-7 absolute, fine for 1e-3 target
    return 2.0f * sigf(2.0f * v) - 1.0f;
}

__global__ void __launch_bounds__(TPB, 2) lstm_fused(
    const float* __restrict__ x,    const float* __restrict__ mask,
    const float* __restrict__ Wih0, const float* __restrict__ Whh0,
    const float* __restrict__ bih0, const float* __restrict__ bhh0,
    const float* __restrict__ Wih1, const float* __restrict__ Whh1,
    const float* __restrict__ bih1, const float* __restrict__ bhh1,
    const float* __restrict__ W1,   const float* __restrict__ b1,
    const float* __restrict__ W2,   const float* __restrict__ b2,
    float* __restrict__ out)
{
    extern __shared__ float smraw[];
    SmemLayout* S = reinterpret_cast<SmemLayout*>(smraw);
    const int tid  = threadIdx.x;
    const int ib   = blockIdx.x % NBK;   // which LSTM block (interleaved for load balance)
    const int tile = blockIdx.x / NBK;
    const int b    = tile * TPB + tid;   // sample index

    // ---- stage weights into SMEM (one-time, coalesced reads) ----
    {
        const float* wih0 = Wih0 + ib * 4 * HD * DIN;
        for (int idx = tid; idx < 4 * HD * DIN; idx += TPB) {
            int r = idx / DIN, k = idx % DIN;
            S->Wp0[r & 31][k][r >> 5] = wih0[idx];
        }
        const float* whh0 = Whh0 + ib * 4 * HD * HD;
        const float* wih1 = Wih1 + ib * 4 * HD * HD;
        const float* whh1 = Whh1 + ib * 4 * HD * HD;
        for (int idx = tid; idx < 4 * HD * HD; idx += TPB) {
            int r = idx / HD, k = idx % HD;
            int j = r & 31, g = r >> 5;
            S->Wh0[j][k][g] = whh0[idx];
            S->Wp1[j][k][g] = wih1[idx];
            S->Wh1[j][k][g] = whh1[idx];
        }
        for (int idx = tid; idx < 4 * HD; idx += TPB) {
            S->b0 [idx & 31][idx >> 5] = bih0[ib * 4 * HD + idx] + bhh0[ib * 4 * HD + idx];
            S->b1r[idx & 31][idx >> 5] = bih1[ib * 4 * HD + idx] + bhh1[ib * 4 * HD + idx];
        }
        for (int idx = tid; idx < HIDD * HD;   idx += TPB) S->W1s[idx] = W1[idx];
        for (int idx = tid; idx < HIDD * HIDD; idx += TPB) S->W2s[idx] = W2[idx];
        if (tid < HIDD) { S->b1s[tid] = b1[tid]; S->b2s[tid] = b2[tid]; }
    }

    // ---- init state ----
    float c0[HD], c1[HD];
#pragma unroll
    for (int j = 0; j < HD; j++) {
        c0[j] = 0.0f; c1[j] = 0.0f;
        S->hs0[j][tid] = 0.0f;
        S->hs1[j][tid] = 0.0f;
    }
    __syncthreads();  // only barrier in the kernel (weights visible)

    const int Ti = 5 * (ib + 1);
    const float4* xp = reinterpret_cast<const float4*>(x)    + (size_t)b * TT + (TT - Ti);
    const float4* mp = reinterpret_cast<const float4*>(mask) + (size_t)b * TT + (TT - Ti);

    float4 xv = __ldg(xp), mv = __ldg(mp);   // prefetch first step
    float hn[HD];

    for (int s = 0; s < Ti; s++) {
        const float xm0 = xv.x * mv.x, xm1 = xv.y * mv.y,
                    xm2 = xv.z * mv.z, xm3 = xv.w * mv.w;
        if (s + 1 < Ti) { xv = __ldg(xp + s + 1); mv = __ldg(mp + s + 1); }

        // ---- layer 0: gates = xm @ Wih0^T + h0 @ Whh0^T + b ----
#pragma unroll
        for (int j = 0; j < HD; j++) {
            float4 bb = *reinterpret_cast<const float4*>(S->b0[j]);
            float ai = bb.x, af = bb.y, ag = bb.z, ao = bb.w;
            float4 w;
            w = *reinterpret_cast<const float4*>(S->Wp0[j][0]);
            ai += xm0 * w.x; af += xm0 * w.y; ag += xm0 * w.z; ao += xm0 * w.w;
            w = *reinterpret_cast<const float4*>(S->Wp0[j][1]);
            ai += xm1 * w.x; af += xm1 * w.y; ag += xm1 * w.z; ao += xm1 * w.w;
            w = *reinterpret_cast<const float4*>(S->Wp0[j][2]);
            ai += xm2 * w.x; af += xm2 * w.y; ag += xm2 * w.z; ao += xm2 * w.w;
            w = *reinterpret_cast<const float4*>(S->Wp0[j][3]);
            ai += xm3 * w.x; af += xm3 * w.y; ag += xm3 * w.z; ao += xm3 * w.w;
#pragma unroll 4
            for (int k = 0; k < HD; k++) {
                float hk  = S->hs0[k][tid];                                    // conflict-free
                float4 ww = *reinterpret_cast<const float4*>(S->Wh0[j][k]);    // broadcast
                ai += hk * ww.x; af += hk * ww.y; ag += hk * ww.z; ao += hk * ww.w;
            }
            float cc = sigf(af) * c0[j] + sigf(ai) * tanhr(ag);
            c0[j] = cc;
            hn[j] = sigf(ao) * tanhr(cc);
        }
#pragma unroll
        for (int j = 0; j < HD; j++) S->hs0[j][tid] = hn[j];

        // ---- layer 1: gates = h0_new @ Wih1^T + h1 @ Whh1^T + b ----
#pragma unroll
        for (int j = 0; j < HD; j++) {
            float4 bb = *reinterpret_cast<const float4*>(S->b1r[j]);
            float ai = bb.x, af = bb.y, ag = bb.z, ao = bb.w;
#pragma unroll 4
            for (int k = 0; k < HD; k++) {
                float hk  = S->hs0[k][tid];
                float4 ww = *reinterpret_cast<const float4*>(S->Wp1[j][k]);
                ai += hk * ww.x; af += hk * ww.y; ag += hk * ww.z; ao += hk * ww.w;
                float gk  = S->hs1[k][tid];
                float4 wv = *reinterpret_cast<const float4*>(S->Wh1[j][k]);
                ai += gk * wv.x; af += gk * wv.y; ag += gk * wv.z; ao += gk * wv.w;
            }
            float cc = sigf(af) * c1[j] + sigf(ai) * tanhr(ag);
            c1[j] = cc;
            hn[j] = sigf(ao) * tanhr(cc);
        }
#pragma unroll
        for (int j = 0; j < HD; j++) S->hs1[j][tid] = hn[j];
    }

    // ---- MLP head: t = gelu(h1 @ W1^T + b1); out = t @ W2^T + b2 ----
    float tg[HIDD];
#pragma unroll
    for (int m = 0; m < HIDD; m++) {
        float acc = S->b1s[m];
#pragma unroll 4
        for (int k = 0; k < HD; k++) acc += S->hs1[k][tid] * S->W1s[m * HD + k];
        // exact gelu: x * 0.5 * (1 + erf(x / sqrt(2)))
        tg[m] = 0.5f * acc * (1.0f + erff(acc * 0.70710678118654752f));
    }
    float* op = out + (size_t)b * (NBK * HIDD) + ib * HIDD;
    for (int n = 0; n < HIDD; n++) {
        float acc = S->b2s[n];
#pragma unroll
        for (int m = 0; m < HIDD; m++) acc += tg[m] * S->W2s[n * HIDD + m];
        op[n] = acc;
    }
}

extern "C" void kernel_launch(void* const* d_in, const int* in_sizes, int n_in,
                              void* d_out, int out_size)
{
    const float* x    = (const float*)d_in[0];
    const float* mask = (const float*)d_in[1];
    const float* Wih0 = (const float*)d_in[2];
    const float* Whh0 = (const float*)d_in[3];
    const float* bih0 = (const float*)d_in[4];
    const float* bhh0 = (const float*)d_in[5];
    const float* Wih1 = (const float*)d_in[6];
    const float* Whh1 = (const float*)d_in[7];
    const float* bih1 = (const float*)d_in[8];
    const float* bhh1 = (const float*)d_in[9];
    const float* W1   = (const float*)d_in[10];
    const float* b1   = (const float*)d_in[11];
    const float* W2   = (const float*)d_in[12];
    const float* b2   = (const float*)d_in[13];
    float* out = (float*)d_out;

    const int Bv = in_sizes[0] / (TT * DIN);        // 32768
    const int grid = (Bv / TPB) * NBK;              // 1280 CTAs
    const size_t smem = sizeof(SmemLayout);         // 110080 B

    cudaFuncSetAttribute(lstm_fused, cudaFuncAttributeMaxDynamicSharedMemorySize,
                         (int)smem);
    lstm_fused<<<grid, TPB, smem>>>(x, mask, Wih0, Whh0, bih0, bhh0,
                                    Wih1, Whh1, bih1, bhh1, W1, b1, W2, b2, out);
}

// round 2
// speedup vs baseline: 1.1997x; 1.1997x over previous
#include <cuda_runtime.h>
#include <math.h>

#define NBK  5     // number of LSTM blocks
#define HD   32    // hidden size
#define DIN  4     // input features
#define TT   25    // total timesteps
#define HIDD 64    // MLP hidden
#define TPB  256   // threads per CTA = samples per CTA
#define JB   16    // j-block (two passes of 16 to bound accumulator registers)

typedef unsigned long long u64;

// Gate weights interleaved [k][j][(i,f,g,o)] so one LDS.128 gives two 64-bit
// packed operands: (w_i,w_f) and (w_g,w_o). State arrays [k][tid]: conflict-free.
struct SmemLayout {
    float Wp0p[DIN][HD][4];   //   512 f : Wih0, [k4][j][g]
    float Wh0p[HD][HD][4];    //  4096 f : Whh0, [k][j][g]
    float Wp1p[HD][HD][4];    //  4096 f : Wih1
    float Wh1p[HD][HD][4];    //  4096 f : Whh1
    float bp0[HD][4];         //   128 f
    float bp1[HD][4];         //   128 f
    float W1s[HIDD * HD];     //  2048 f
    float b1s[HIDD];          //    64 f
    float W2t[HIDD * HIDD];   //  4096 f : W2 transposed [m][n]
    float b2s[HIDD];          //    64 f
    float h0s[HD][TPB];       //  8192 f   (h0s+c0s reused as tg[64] in MLP)
    float c0s[HD][TPB];       //  8192 f
    float h1s[HD][TPB];       //  8192 f
    float c1s[HD][TPB];       //  8192 f
};                            // 52096 floats = 208384 B -> 1 CTA/SM (8 warps)

__device__ __forceinline__ u64 pk2(float v) {
    u64 r; asm("mov.b64 %0, {%1, %1};" : "=l"(r) : "f"(v)); return r;
}
__device__ __forceinline__ u64 f2fma(u64 a, u64 b, u64 c) {
    u64 d; asm("fma.rn.f32x2 %0, %1, %2, %3;" : "=l"(d) : "l"(a), "l"(b), "l"(c));
    return d;
}
__device__ __forceinline__ void unpk(u64 v, float& lo, float& hi) {
    asm("mov.b64 {%0, %1}, %2;" : "=f"(lo), "=f"(hi) : "l"(v));
}
__device__ __forceinline__ float sigf(float v) {
    return 1.0f / (1.0f + __expf(-v));
}
__device__ __forceinline__ float tanhr(float v) {
    return 2.0f * sigf(2.0f * v) - 1.0f;
}

__global__ void __launch_bounds__(TPB, 1) lstm_fused(
    const float* __restrict__ x,    const float* __restrict__ mask,
    const float* __restrict__ Wih0, const float* __restrict__ Whh0,
    const float* __restrict__ bih0, const float* __restrict__ bhh0,
    const float* __restrict__ Wih1, const float* __restrict__ Whh1,
    const float* __restrict__ bih1, const float* __restrict__ bhh1,
    const float* __restrict__ W1,   const float* __restrict__ b1,
    const float* __restrict__ W2,   const float* __restrict__ b2,
    float* __restrict__ out)
{
    extern __shared__ float smraw[];
    SmemLayout* S = reinterpret_cast<SmemLayout*>(smraw);
    const int tid = threadIdx.x;
    const int ib  = blockIdx.x % NBK;
    const int b   = (blockIdx.x / NBK) * TPB + tid;

    // ---- stage weights (interleaved) ----
    {
        const float* wih0 = Wih0 + ib * 4 * HD * DIN;
        for (int idx = tid; idx < 4 * HD * DIN; idx += TPB) {
            int r = idx / DIN, k4 = idx % DIN, g = r >> 5, j = r & 31;
            S->Wp0p[k4][j][g] = wih0[idx];
        }
        const float* whh0 = Whh0 + ib * 4 * HD * HD;
        const float* wih1 = Wih1 + ib * 4 * HD * HD;
        const float* whh1 = Whh1 + ib * 4 * HD * HD;
        for (int idx = tid; idx < 4 * HD * HD; idx += TPB) {
            int r = idx / HD, k = idx % HD, g = r >> 5, j = r & 31;
            S->Wh0p[k][j][g] = whh0[idx];
            S->Wp1p[k][j][g] = wih1[idx];
            S->Wh1p[k][j][g] = whh1[idx];
        }
        for (int idx = tid; idx < 4 * HD; idx += TPB) {
            int g = idx >> 5, j = idx & 31;
            S->bp0[j][g] = bih0[ib * 4 * HD + idx] + bhh0[ib * 4 * HD + idx];
            S->bp1[j][g] = bih1[ib * 4 * HD + idx] + bhh1[ib * 4 * HD + idx];
        }
        for (int idx = tid; idx < HIDD * HD; idx += TPB) S->W1s[idx] = W1[idx];
        for (int idx = tid; idx < HIDD * HIDD; idx += TPB) {
            int n = idx / HIDD, m = idx % HIDD;
            S->W2t[m * HIDD + n] = W2[idx];       // transpose for vector epilogue
        }
        if (tid < HIDD) { S->b1s[tid] = b1[tid]; S->b2s[tid] = b2[tid]; }
    }

    // ---- init state ----
#pragma unroll
    for (int j = 0; j < HD; j++) {
        S->h0s[j][tid] = 0.0f; S->c0s[j][tid] = 0.0f;
        S->h1s[j][tid] = 0.0f; S->c1s[j][tid] = 0.0f;
    }
    __syncthreads();

    const int Ti = 5 * (ib + 1);
    const float4* xp = reinterpret_cast<const float4*>(x)    + (size_t)b * TT + (TT - Ti);
    const float4* mp = reinterpret_cast<const float4*>(mask) + (size_t)b * TT + (TT - Ti);
    float4 xv = __ldg(xp), mv = __ldg(mp);

    float hn[HD];

    for (int s = 0; s < Ti; s++) {
        u64 xm2[DIN];
        xm2[0] = pk2(xv.x * mv.x); xm2[1] = pk2(xv.y * mv.y);
        xm2[2] = pk2(xv.z * mv.z); xm2[3] = pk2(xv.w * mv.w);
        if (s + 1 < Ti) { xv = __ldg(xp + s + 1); mv = __ldg(mp + s + 1); }

        // ================= layer 0 =================
#pragma unroll
        for (int jb = 0; jb < 2; jb++) {
            u64 aif[JB], ago[JB];
#pragma unroll
            for (int jj = 0; jj < JB; jj++) {
                ulonglong2 bb = *reinterpret_cast<const ulonglong2*>(S->bp0[jb * JB + jj]);
                aif[jj] = bb.x; ago[jj] = bb.y;
            }
#pragma unroll
            for (int k = 0; k < DIN; k++) {
                u64 hk2 = xm2[k];
#pragma unroll
                for (int jj = 0; jj < JB; jj++) {
                    ulonglong2 w = *reinterpret_cast<const ulonglong2*>(S->Wp0p[k][jb * JB + jj]);
                    aif[jj] = f2fma(w.x, hk2, aif[jj]);
                    ago[jj] = f2fma(w.y, hk2, ago[jj]);
                }
            }
            for (int k = 0; k < HD; k++) {
                u64 hk2 = pk2(S->h0s[k][tid]);
#pragma unroll
                for (int jj = 0; jj < JB; jj++) {
                    ulonglong2 w = *reinterpret_cast<const ulonglong2*>(S->Wh0p[k][jb * JB + jj]);
                    aif[jj] = f2fma(w.x, hk2, aif[jj]);
                    ago[jj] = f2fma(w.y, hk2, ago[jj]);
                }
            }
#pragma unroll
            for (int jj = 0; jj < JB; jj++) {
                const int j = jb * JB + jj;
                float ai, af, ag, ao;
                unpk(aif[jj], ai, af); unpk(ago[jj], ag, ao);
                float cc = sigf(af) * S->c0s[j][tid] + sigf(ai) * tanhr(ag);
                S->c0s[j][tid] = cc;
                hn[j] = sigf(ao) * tanhr(cc);
            }
        }
#pragma unroll
        for (int j = 0; j < HD; j++) S->h0s[j][tid] = hn[j];

        // ================= layer 1 =================
#pragma unroll
        for (int jb = 0; jb < 2; jb++) {
            u64 aif[JB], ago[JB];
#pragma unroll
            for (int jj = 0; jj < JB; jj++) {
                ulonglong2 bb = *reinterpret_cast<const ulonglong2*>(S->bp1[jb * JB + jj]);
                aif[jj] = bb.x; ago[jj] = bb.y;
            }
            for (int k = 0; k < HD; k++) {
                u64 hk2 = pk2(S->h0s[k][tid]);
#pragma unroll
                for (int jj = 0; jj < JB; jj++) {
                    ulonglong2 w = *reinterpret_cast<const ulonglong2*>(S->Wp1p[k][jb * JB + jj]);
                    aif[jj] = f2fma(w.x, hk2, aif[jj]);
                    ago[jj] = f2fma(w.y, hk2, ago[jj]);
                }
            }
            for (int k = 0; k < HD; k++) {
                u64 hk2 = pk2(S->h1s[k][tid]);
#pragma unroll
                for (int jj = 0; jj < JB; jj++) {
                    ulonglong2 w = *reinterpret_cast<const ulonglong2*>(S->Wh1p[k][jb * JB + jj]);
                    aif[jj] = f2fma(w.x, hk2, aif[jj]);
                    ago[jj] = f2fma(w.y, hk2, ago[jj]);
                }
            }
#pragma unroll
            for (int jj = 0; jj < JB; jj++) {
                const int j = jb * JB + jj;
                float ai, af, ag, ao;
                unpk(aif[jj], ai, af); unpk(ago[jj], ag, ao);
                float cc = sigf(af) * S->c1s[j][tid] + sigf(ai) * tanhr(ag);
                S->c1s[j][tid] = cc;
                hn[j] = sigf(ao) * tanhr(cc);
            }
        }
#pragma unroll
        for (int j = 0; j < HD; j++) S->h1s[j][tid] = hn[j];
    }

    // ---- MLP head ----
    __syncthreads();   // everyone done with weight smem before tg reuse

    float h1r[HD];
#pragma unroll
    for (int k = 0; k < HD; k++) h1r[k] = S->h1s[k][tid];

    // tg staged into dead state smem (h0s + c0s = 64 rows x TPB, adjacent)
    float* tgS = &S->h0s[0][0];

    for (int m = 0; m < HIDD; m++) {
        float acc = S->b1s[m];
        const float4* wr = reinterpret_cast<const float4*>(&S->W1s[m * HD]);
#pragma unroll
        for (int q = 0; q < HD / 4; q++) {
            float4 w = wr[q];
            acc += h1r[4 * q + 0] * w.x; acc += h1r[4 * q + 1] * w.y;
            acc += h1r[4 * q + 2] * w.z; acc += h1r[4 * q + 3] * w.w;
        }
        tgS[m * TPB + tid] = 0.5f * acc * (1.0f + erff(acc * 0.70710678118654752f));
    }

    float acc2[HIDD];
#pragma unroll
    for (int n = 0; n < HIDD; n++) acc2[n] = S->b2s[n];
    for (int m = 0; m < HIDD; m++) {
        float tgv = tgS[m * TPB + tid];
        const float4* w2r = reinterpret_cast<const float4*>(&S->W2t[m * HIDD]);
#pragma unroll
        for (int n4 = 0; n4 < HIDD / 4; n4++) {
            float4 w = w2r[n4];
            acc2[4 * n4 + 0] += tgv * w.x; acc2[4 * n4 + 1] += tgv * w.y;
            acc2[4 * n4 + 2] += tgv * w.z; acc2[4 * n4 + 3] += tgv * w.w;
        }
    }

    float4* op = reinterpret_cast<float4*>(out + (size_t)b * (NBK * HIDD) + ib * HIDD);
#pragma unroll
    for (int n4 = 0; n4 < HIDD / 4; n4++)
        op[n4] = make_float4(acc2[4 * n4], acc2[4 * n4 + 1],
                             acc2[4 * n4 + 2], acc2[4 * n4 + 3]);
}

extern "C" void kernel_launch(void* const* d_in, const int* in_sizes, int n_in,
                              void* d_out, int out_size)
{
    const float* x    = (const float*)d_in[0];
    const float* mask = (const float*)d_in[1];
    const float* Wih0 = (const float*)d_in[2];
    const float* Whh0 = (const float*)d_in[3];
    const float* bih0 = (const float*)d_in[4];
    const float* bhh0 = (const float*)d_in[5];
    const float* Wih1 = (const float*)d_in[6];
    const float* Whh1 = (const float*)d_in[7];
    const float* bih1 = (const float*)d_in[8];
    const float* bhh1 = (const float*)d_in[9];
    const float* W1   = (const float*)d_in[10];
    const float* b1   = (const float*)d_in[11];
    const float* W2   = (const float*)d_in[12];
    const float* b2   = (const float*)d_in[13];
    float* out = (float*)d_out;

    const int Bv = in_sizes[0] / (TT * DIN);        // 32768
    const int grid = (Bv / TPB) * NBK;              // 640 CTAs
    const size_t smem = sizeof(SmemLayout);         // 208384 B

    cudaFuncSetAttribute(lstm_fused, cudaFuncAttributeMaxDynamicSharedMemorySize,
                         (int)smem);
    lstm_fused<<<grid, TPB, smem>>>(x, mask, Wih0, Whh0, bih0, bhh0,
                                    Wih1, Whh1, bih1, bhh1, W1, b1, W2, b2, out);
}

// round 3
// speedup vs baseline: 1.3232x; 1.1030x over previous
#include <cuda_runtime.h>
#include <math.h>

#define NBK  5
#define HD   32
#define DIN  4
#define TT   25
#define HIDD 64
#define TPB  128          // threads per CTA
#define SPT  2            // samples per thread
#define SPC  (TPB*SPT)    // 256 samples per CTA
#define TILES 128         // 32768 / 256
#define GRID (TILES*NBK)  // 640
#define JB   4            // j-block per pass
#define NPASS (HD/JB)     // 8

typedef unsigned long long u64;

// Weights interleaved [k][j][(i,f,g,o)] -> one LDS.128 = 4 gate weights of (k,j),
// reused by both samples: 16B per 8 FMAs.
struct SmemLayout {
    float Wp0p[DIN][HD][4];   //  2048 B
    float Wh0p[HD][HD][4];    // 16384 B
    float Wp1p[HD][HD][4];    // 16384 B
    float Wh1p[HD][HD][4];    // 16384 B
    float bp0[HD][4];         //   512 B
    float bp1[HD][4];         //   512 B
    float2 h1s[HD][TPB];      // 32768 B  (layer-1 h state, packed (a,b))
};                            // 84992 B -> 2 CTAs/SM

// MLP-weight overlay offsets (floats) into the weights region after recurrence:
#define OV_W1 0
#define OV_B1 2048
#define OV_W2 2112
#define OV_B2 6208

// c-state scratch in L2 (per CTA: 2 layers x 32 j x 128 tid, packed (a,b))
__device__ float2 g_cst[GRID][2][HD][TPB];

__device__ __forceinline__ u64 pk2(float v) {
    u64 r; asm("mov.b64 %0, {%1, %1};" : "=l"(r) : "f"(v)); return r;
}
__device__ __forceinline__ u64 f2fma(u64 a, u64 b, u64 c) {
    u64 d; asm("fma.rn.f32x2 %0, %1, %2, %3;" : "=l"(d) : "l"(a), "l"(b), "l"(c));
    return d;
}
__device__ __forceinline__ void unpk(u64 v, float& lo, float& hi) {
    asm("mov.b64 {%0, %1}, %2;" : "=f"(lo), "=f"(hi) : "l"(v));
}
__device__ __forceinline__ float sigf(float v) {
    return __fdividef(1.0f, 1.0f + __expf(-v));
}
__device__ __forceinline__ float tanhr(float v) {
    return __fdividef(2.0f, 1.0f + __expf(-2.0f * v)) - 1.0f;
}

__global__ void __launch_bounds__(TPB, 2) lstm_fused(
    const float* __restrict__ x,    const float* __restrict__ mask,
    const float* __restrict__ Wih0, const float* __restrict__ Whh0,
    const float* __restrict__ bih0, const float* __restrict__ bhh0,
    const float* __restrict__ Wih1, const float* __restrict__ Whh1,
    const float* __restrict__ bih1, const float* __restrict__ bhh1,
    const float* __restrict__ W1,   const float* __restrict__ b1,
    const float* __restrict__ W2,   const float* __restrict__ b2,
    float* __restrict__ out)
{
    extern __shared__ float smraw[];
    SmemLayout* S = reinterpret_cast<SmemLayout*>(smraw);
    const int tid  = threadIdx.x;
    const int ib   = 4 - (blockIdx.x >> 7);   // heavy blocks launch first
    const int tile = blockIdx.x & (TILES - 1);
    const int bA   = tile * SPC + tid;        // sample A
    const int bB   = bA + TPB;                // sample B

    float2* gc0 = &g_cst[blockIdx.x][0][0][0];
    float2* gc1 = &g_cst[blockIdx.x][1][0][0];

    // ---- stage weights into SMEM (interleaved) ----
    {
        const float* wih0 = Wih0 + ib * 4 * HD * DIN;
        for (int idx = tid; idx < 4 * HD * DIN; idx += TPB) {
            int r = idx / DIN, k = idx % DIN, g = r >> 5, j = r & 31;
            S->Wp0p[k][j][g] = wih0[idx];
        }
        const float* whh0 = Whh0 + ib * 4 * HD * HD;
        const float* wih1 = Wih1 + ib * 4 * HD * HD;
        const float* whh1 = Whh1 + ib * 4 * HD * HD;
        for (int idx = tid; idx < 4 * HD * HD; idx += TPB) {
            int r = idx / HD, k = idx % HD, g = r >> 5, j = r & 31;
            S->Wh0p[k][j][g] = whh0[idx];
            S->Wp1p[k][j][g] = wih1[idx];
            S->Wh1p[k][j][g] = whh1[idx];
        }
        for (int idx = tid; idx < 4 * HD; idx += TPB) {
            int g = idx >> 5, j = idx & 31;
            S->bp0[j][g] = bih0[ib * 4 * HD + idx] + bhh0[ib * 4 * HD + idx];
            S->bp1[j][g] = bih1[ib * 4 * HD + idx] + bhh1[ib * 4 * HD + idx];
        }
    }
    // init h1 state (own column only, but sync below covers visibility of weights)
#pragma unroll
    for (int j = 0; j < HD; j++) S->h1s[j][tid] = make_float2(0.0f, 0.0f);
    __syncthreads();

    // ---- register state ----
    float h0a[HD], h0b[HD], na[HD], nb[HD];
#pragma unroll
    for (int j = 0; j < HD; j++) { h0a[j] = 0.0f; h0b[j] = 0.0f; }

    const int Ti = 5 * (ib + 1);
    const float4* xpa = reinterpret_cast<const float4*>(x)    + (size_t)bA * TT + (TT - Ti);
    const float4* mpa = reinterpret_cast<const float4*>(mask) + (size_t)bA * TT + (TT - Ti);
    const float4* xpb = reinterpret_cast<const float4*>(x)    + (size_t)bB * TT + (TT - Ti);
    const float4* mpb = reinterpret_cast<const float4*>(mask) + (size_t)bB * TT + (TT - Ti);
    float4 xva = __ldg(xpa), mva = __ldg(mpa);
    float4 xvb = __ldg(xpb), mvb = __ldg(mpb);

    for (int s = 0; s < Ti; s++) {
        u64 xma2[DIN], xmb2[DIN];
        xma2[0] = pk2(xva.x * mva.x); xma2[1] = pk2(xva.y * mva.y);
        xma2[2] = pk2(xva.z * mva.z); xma2[3] = pk2(xva.w * mva.w);
        xmb2[0] = pk2(xvb.x * mvb.x); xmb2[1] = pk2(xvb.y * mvb.y);
        xmb2[2] = pk2(xvb.z * mvb.z); xmb2[3] = pk2(xvb.w * mvb.w);
        if (s + 1 < Ti) {
            xva = __ldg(xpa + s + 1); mva = __ldg(mpa + s + 1);
            xvb = __ldg(xpb + s + 1); mvb = __ldg(mpb + s + 1);
        }

        // ================= layer 0 =================
#pragma unroll
        for (int p = 0; p < NPASS; p++) {
            u64 iA[JB], gA[JB], iB[JB], gB[JB];
            float2 cp[JB];
#pragma unroll
            for (int q = 0; q < JB; q++) {
                const int j = p * JB + q;
                ulonglong2 bb = *reinterpret_cast<const ulonglong2*>(S->bp0[j]);
                iA[q] = bb.x; gA[q] = bb.y; iB[q] = bb.x; gB[q] = bb.y;
                cp[q] = (s == 0) ? make_float2(0.0f, 0.0f) : gc0[j * TPB + tid];
            }
#pragma unroll
            for (int k = 0; k < DIN; k++) {
#pragma unroll
                for (int q = 0; q < JB; q++) {
                    ulonglong2 w = *reinterpret_cast<const ulonglong2*>(S->Wp0p[k][p * JB + q]);
                    iA[q] = f2fma(w.x, xma2[k], iA[q]); gA[q] = f2fma(w.y, xma2[k], gA[q]);
                    iB[q] = f2fma(w.x, xmb2[k], iB[q]); gB[q] = f2fma(w.y, xmb2[k], gB[q]);
                }
            }
#pragma unroll
            for (int k = 0; k < HD; k++) {
                u64 ha = pk2(h0a[k]), hb = pk2(h0b[k]);
#pragma unroll
                for (int q = 0; q < JB; q++) {
                    ulonglong2 w = *reinterpret_cast<const ulonglong2*>(S->Wh0p[k][p * JB + q]);
                    iA[q] = f2fma(w.x, ha, iA[q]); gA[q] = f2fma(w.y, ha, gA[q]);
                    iB[q] = f2fma(w.x, hb, iB[q]); gB[q] = f2fma(w.y, hb, gB[q]);
                }
            }
#pragma unroll
            for (int q = 0; q < JB; q++) {
                const int j = p * JB + q;
                float ai, af, ag, ao, bi, bf, bg, bo;
                unpk(iA[q], ai, af); unpk(gA[q], ag, ao);
                unpk(iB[q], bi, bf); unpk(gB[q], bg, bo);
                float ca = sigf(af) * cp[q].x + sigf(ai) * tanhr(ag);
                float cb = sigf(bf) * cp[q].y + sigf(bi) * tanhr(bg);
                gc0[j * TPB + tid] = make_float2(ca, cb);
                na[j] = sigf(ao) * tanhr(ca);
                nb[j] = sigf(bo) * tanhr(cb);
            }
        }
#pragma unroll
        for (int j = 0; j < HD; j++) { h0a[j] = na[j]; h0b[j] = nb[j]; }

        // ================= layer 1 =================
#pragma unroll
        for (int p = 0; p < NPASS; p++) {
            u64 iA[JB], gA[JB], iB[JB], gB[JB];
            float2 cp[JB];
#pragma unroll
            for (int q = 0; q < JB; q++) {
                const int j = p * JB + q;
                ulonglong2 bb = *reinterpret_cast<const ulonglong2*>(S->bp1[j]);
                iA[q] = bb.x; gA[q] = bb.y; iB[q] = bb.x; gB[q] = bb.y;
                cp[q] = (s == 0) ? make_float2(0.0f, 0.0f) : gc1[j * TPB + tid];
            }
#pragma unroll
            for (int k = 0; k < HD; k++) {           // input = new h0 (regs)
                u64 ha = pk2(h0a[k]), hb = pk2(h0b[k]);
#pragma unroll
                for (int q = 0; q < JB; q++) {
                    ulonglong2 w = *reinterpret_cast<const ulonglong2*>(S->Wp1p[k][p * JB + q]);
                    iA[q] = f2fma(w.x, ha, iA[q]); gA[q] = f2fma(w.y, ha, gA[q]);
                    iB[q] = f2fma(w.x, hb, iB[q]); gB[q] = f2fma(w.y, hb, gB[q]);
                }
            }
#pragma unroll
            for (int k = 0; k < HD; k++) {           // recurrent = h1 (smem)
                float2 hv = S->h1s[k][tid];
                u64 ha = pk2(hv.x), hb = pk2(hv.y);
#pragma unroll
                for (int q = 0; q < JB; q++) {
                    ulonglong2 w = *reinterpret_cast<const ulonglong2*>(S->Wh1p[k][p * JB + q]);
                    iA[q] = f2fma(w.x, ha, iA[q]); gA[q] = f2fma(w.y, ha, gA[q]);
                    iB[q] = f2fma(w.x, hb, iB[q]); gB[q] = f2fma(w.y, hb, gB[q]);
                }
            }
#pragma unroll
            for (int q = 0; q < JB; q++) {
                const int j = p * JB + q;
                float ai, af, ag, ao, bi, bf, bg, bo;
                unpk(iA[q], ai, af); unpk(gA[q], ag, ao);
                unpk(iB[q], bi, bf); unpk(gB[q], bg, bo);
                float ca = sigf(af) * cp[q].x + sigf(ai) * tanhr(ag);
                float cb = sigf(bf) * cp[q].y + sigf(bi) * tanhr(bg);
                gc1[j * TPB + tid] = make_float2(ca, cb);
                na[j] = sigf(ao) * tanhr(ca);         // na/nb now hold new h1
                nb[j] = sigf(bo) * tanhr(cb);
            }
        }
#pragma unroll
        for (int j = 0; j < HD; j++) S->h1s[j][tid] = make_float2(na[j], nb[j]);
    }

    // ---- MLP head: stage W1/W2 into dead gate-weight smem ----
    __syncthreads();
    float* ov = smraw;   // overlay at base of weights region
    for (int idx = tid; idx < HIDD * HD; idx += TPB)   ov[OV_W1 + idx] = W1[idx];
    for (int idx = tid; idx < HIDD * HIDD; idx += TPB) {
        int n = idx / HIDD, m = idx % HIDD;
        ov[OV_W2 + m * HIDD + n] = W2[idx];            // transposed [m][n]
    }
    if (tid < HIDD) { ov[OV_B1 + tid] = b1[tid]; ov[OV_B2 + tid] = b2[tid]; }
    __syncthreads();

    // na/nb hold final h1 for samples A/B
#pragma unroll
    for (int smp = 0; smp < 2; smp++) {
        const float* hr = (smp == 0) ? na : nb;
        float acc2[HIDD];
#pragma unroll
        for (int n = 0; n < HIDD; n++) acc2[n] = ov[OV_B2 + n];
        for (int m = 0; m < HIDD; m++) {
            float tm = ov[OV_B1 + m];
            const float4* w1r = reinterpret_cast<const float4*>(&ov[OV_W1 + m * HD]);
#pragma unroll
            for (int q = 0; q < HD / 4; q++) {
                float4 w = w1r[q];
                tm += hr[4 * q + 0] * w.x + hr[4 * q + 1] * w.y
                    + hr[4 * q + 2] * w.z + hr[4 * q + 3] * w.w;
            }
            tm = 0.5f * tm * (1.0f + erff(tm * 0.70710678118654752f));
            const float4* w2r = reinterpret_cast<const float4*>(&ov[OV_W2 + m * HIDD]);
#pragma unroll
            for (int q = 0; q < HIDD / 4; q++) {
                float4 w = w2r[q];
                acc2[4 * q + 0] += tm * w.x; acc2[4 * q + 1] += tm * w.y;
                acc2[4 * q + 2] += tm * w.z; acc2[4 * q + 3] += tm * w.w;
            }
        }
        const int b = (smp == 0) ? bA : bB;
        float4* op = reinterpret_cast<float4*>(out + ((size_t)b * NBK + ib) * HIDD);
#pragma unroll
        for (int q = 0; q < HIDD / 4; q++)
            op[q] = make_float4(acc2[4 * q], acc2[4 * q + 1],
                                acc2[4 * q + 2], acc2[4 * q + 3]);
    }
}

extern "C" void kernel_launch(void* const* d_in, const int* in_sizes, int n_in,
                              void* d_out, int out_size)
{
    const float* x    = (const float*)d_in[0];
    const float* mask = (const float*)d_in[1];
    const float* Wih0 = (const float*)d_in[2];
    const float* Whh0 = (const float*)d_in[3];
    const float* bih0 = (const float*)d_in[4];
    const float* bhh0 = (const float*)d_in[5];
    const float* Wih1 = (const float*)d_in[6];
    const float* Whh1 = (const float*)d_in[7];
    const float* bih1 = (const float*)d_in[8];
    const float* bhh1 = (const float*)d_in[9];
    const float* W1   = (const float*)d_in[10];
    const float* b1   = (const float*)d_in[11];
    const float* W2   = (const float*)d_in[12];
    const float* b2   = (const float*)d_in[13];
    float* out = (float*)d_out;

    const size_t smem = sizeof(SmemLayout);   // 84992 B -> 2 CTAs/SM
    cudaFuncSetAttribute(lstm_fused, cudaFuncAttributeMaxDynamicSharedMemorySize,
                         (int)smem);
    lstm_fused<<<GRID, TPB, smem>>>(x, mask, Wih0, Whh0, bih0, bhh0,
                                    Wih1, Whh1, bih1, bhh1, W1, b1, W2, b2, out);
}